// round 6
// baseline (speedup 1.0000x reference)
#include <cuda_runtime.h>
#include <math.h>
#include <stdint.h>

#define NTOK 65536
#define CIN 192
#define HID 384
#define OUTD 192
#define NE 8
#define KCAP 10240
#define SSTR 68
#define LSCALE 2.0f  /* alpha/r = 16/8 */

typedef unsigned long long ull;

__device__ __forceinline__ ull pk2(float lo, float hi) {
    ull r; asm("mov.b64 %0,{%1,%2};" : "=l"(r) : "f"(lo), "f"(hi)); return r;
}
__device__ __forceinline__ void upk2(ull v, float& lo, float& hi) {
    asm("mov.b64 {%0,%1},%2;" : "=f"(lo), "=f"(hi) : "l"(v));
}
__device__ __forceinline__ void fma2(ull& d, ull a, ull b) {
    asm("fma.rn.f32x2 %0,%1,%2,%0;" : "+l"(d) : "l"(a), "l"(b));
}

// ---------------- device scratch ----------------
__device__ float    g_logits[NE * NTOK];
__device__ unsigned g_mask[NTOK];
__device__ int      g_cnt[NE];
__device__ int      g_list[NE * NTOK];
__device__ float    g_wl[NE * NTOK];
__device__ unsigned g_te[NTOK];
__device__ float    g_tw0[NTOK];
__device__ float    g_tw1[NTOK];

__global__ void init_kernel() {
    if (threadIdx.x < NE) g_cnt[threadIdx.x] = 0;
}

// ---------------- gate: features + LN + logits ----------------
__global__ void __launch_bounds__(1024) gate_kernel(
    const float* __restrict__ x, const float* __restrict__ xprev,
    const float* __restrict__ Wz, const float* __restrict__ lng,
    const float* __restrict__ lnb, const float* __restrict__ Wg,
    const float* __restrict__ bg)
{
    extern __shared__ float sm[];
    float* sWz = sm;            // 12288
    float* sWg = sWz + 12288;   // 2064
    float* sg  = sWg + 2064;    // 258
    float* sb  = sg + 258;      // 258
    float* sbg = sb + 258;      // 8
    float* sX  = sbg + 8;       // 32*192

    int tid = threadIdx.x, lane = tid & 31, warp = tid >> 5;
    int n = blockIdx.x * 32 + warp;

    for (int i = tid; i < 12288; i += 1024) sWz[i] = Wz[i];
    for (int i = tid; i < 2064;  i += 1024) sWg[i] = Wg[i];
    for (int i = tid; i < 258;   i += 1024) { sg[i] = lng[i]; sb[i] = lnb[i]; }
    if (tid < 8) sbg[tid] = bg[tid];

    float xr[6];
    #pragma unroll
    for (int i = 0; i < 6; i++) {
        xr[i] = x[(size_t)n*CIN + lane + 32*i];
        sX[warp*CIN + lane + 32*i] = xr[i];
    }
    float s = 0.f, ss = 0.f;
    #pragma unroll
    for (int i = 0; i < 6; i++) {
        float a = fabsf(xr[i] - xprev[(size_t)n*CIN + lane + 32*i]);
        s += a; ss += a*a;
    }
    #pragma unroll
    for (int o = 16; o; o >>= 1) {
        s  += __shfl_xor_sync(0xffffffffu, s, o);
        ss += __shfl_xor_sync(0xffffffffu, ss, o);
    }
    float dmean = s * (1.0f/192.0f);
    float dvar  = fmaxf((ss - s*dmean) * (1.0f/191.0f), 0.f);
    float mu = log1pf(dmean), sd = log1pf(sqrtf(dvar));

    __syncthreads();

    float z0 = 0.f, z1 = 0.f;
    for (int c = 0; c < CIN; c++) {
        float xv = sX[warp*CIN + c];
        z0 = fmaf(xv, sWz[c*64 + lane],      z0);
        z1 = fmaf(xv, sWz[c*64 + lane + 32], z1);
    }
    float sa = z0 + z1, s2 = z0*z0 + z1*z1;
    #pragma unroll
    for (int i = 0; i < 6; i++) { sa += xr[i]; s2 += xr[i]*xr[i]; }
    if (lane == 0) { sa += mu + sd; s2 += mu*mu + sd*sd; }
    #pragma unroll
    for (int o = 16; o; o >>= 1) {
        sa += __shfl_xor_sync(0xffffffffu, sa, o);
        s2 += __shfl_xor_sync(0xffffffffu, s2, o);
    }
    float m_   = sa * (1.0f/258.0f);
    float rstd = rsqrtf(s2 * (1.0f/258.0f) - m_*m_ + 1e-5f);

    float acc[8] = {0,0,0,0,0,0,0,0};
    #pragma unroll
    for (int i = 0; i < 6; i++) {
        int idx = lane + 32*i;
        float nv = (xr[i] - m_)*rstd*sg[idx] + sb[idx];
        #pragma unroll
        for (int e = 0; e < 8; e++) acc[e] = fmaf(nv, sWg[idx*8 + e], acc[e]);
    }
    {
        int idx = 192 + lane;
        float nv = (z0 - m_)*rstd*sg[idx] + sb[idx];
        #pragma unroll
        for (int e = 0; e < 8; e++) acc[e] = fmaf(nv, sWg[idx*8 + e], acc[e]);
        idx = 224 + lane;
        nv = (z1 - m_)*rstd*sg[idx] + sb[idx];
        #pragma unroll
        for (int e = 0; e < 8; e++) acc[e] = fmaf(nv, sWg[idx*8 + e], acc[e]);
    }
    if (lane == 0) {
        float nv = (mu - m_)*rstd*sg[256] + sb[256];
        #pragma unroll
        for (int e = 0; e < 8; e++) acc[e] = fmaf(nv, sWg[256*8 + e], acc[e]);
        nv = (sd - m_)*rstd*sg[257] + sb[257];
        #pragma unroll
        for (int e = 0; e < 8; e++) acc[e] = fmaf(nv, sWg[257*8 + e], acc[e]);
    }
    #pragma unroll
    for (int e = 0; e < 8; e++) {
        #pragma unroll
        for (int o = 16; o; o >>= 1) acc[e] += __shfl_xor_sync(0xffffffffu, acc[e], o);
    }
    if (lane == 0) {
        #pragma unroll
        for (int e = 0; e < 8; e++) g_logits[e*NTOK + n] = acc[e] + sbg[e];
        g_mask[n] = 0u;
    }
}

// ---------------- expert-choice: radix select top-K per expert ----------------
__device__ __forceinline__ unsigned f2key(float f) {
    unsigned u = __float_as_uint(f);
    return (u & 0x80000000u) ? ~u : (u | 0x80000000u);
}

__global__ void __launch_bounds__(1024) select_kernel() {
    __shared__ unsigned hist[256];
    __shared__ unsigned sh_digit, sh_need;
    __shared__ int ccount[64];
    __shared__ int cbase[64];

    int e = blockIdx.x, tid = threadIdx.x;
    int lane = tid & 31, warp = tid >> 5;
    const float* base = g_logits + (size_t)e * NTOK;

    unsigned prefix = 0, pmask = 0, need = KCAP;
    for (int pass = 0; pass < 4; pass++) {
        int shift = 24 - pass*8;
        if (tid < 256) hist[tid] = 0;
        __syncthreads();
        for (int n = tid; n < NTOK; n += 1024) {
            unsigned k = f2key(base[n]);
            bool act = ((k & pmask) == prefix);
            unsigned dg = act ? ((k >> shift) & 255u) : 0xffffffffu;
            unsigned peers = __match_any_sync(0xffffffffu, dg);
            if (act && (__ffs(peers) - 1) == lane)
                atomicAdd(&hist[dg], (unsigned)__popc(peers));
        }
        __syncthreads();
        if (tid == 0) {
            unsigned cum = 0; int d = 255;
            for (; d > 0; d--) {
                unsigned h = hist[d];
                if (cum + h >= need) break;
                cum += h;
            }
            sh_digit = (unsigned)d;
            sh_need  = need - cum;
        }
        __syncthreads();
        prefix |= sh_digit << shift;
        pmask  |= 0xFFu << shift;
        need    = sh_need;
        __syncthreads();
    }
    unsigned thr = prefix;
    int r = (int)need;   // count of ==thr keys to take, lowest index first

    for (int n = tid; n < NTOK; n += 1024)
        if (f2key(base[n]) > thr) atomicOr(&g_mask[n], 1u << e);

    for (int c = warp; c < 64; c += 32) {
        int cnt = 0;
        for (int s = 0; s < 32; s++) {
            int n = c*1024 + s*32 + lane;
            cnt += (f2key(base[n]) == thr);
        }
        #pragma unroll
        for (int o = 16; o; o >>= 1) cnt += __shfl_xor_sync(0xffffffffu, cnt, o);
        if (lane == 0) ccount[c] = cnt;
    }
    __syncthreads();
    if (tid == 0) {
        int run = 0;
        for (int c = 0; c < 64; c++) { cbase[c] = run; run += ccount[c]; }
    }
    __syncthreads();
    for (int c = warp; c < 64; c += 32) {
        int rank = cbase[c];
        if (rank >= r) continue;
        for (int s = 0; s < 32; s++) {
            int n = c*1024 + s*32 + lane;
            bool p = (f2key(base[n]) == thr);
            unsigned bal = __ballot_sync(0xffffffffu, p);
            int myrank = rank + __popc(bal & ((1u << lane) - 1u));
            if (p && myrank < r) atomicOr(&g_mask[n], 1u << e);
            rank += __popc(bal);
        }
    }
}

// ---------------- routing (block-aggregated dispatch) ----------------
__global__ void __launch_bounds__(256) route_kernel(float* __restrict__ out) {
    __shared__ int sCnt[8], sBase[8];
    int tid = threadIdx.x;
    int n = blockIdx.x * 256 + tid;
    if (tid < 8) sCnt[tid] = 0;
    __syncthreads();

    float l[8];
    #pragma unroll
    for (int e = 0; e < 8; e++) l[e] = g_logits[e*NTOK + n];
    unsigned m = g_mask[n];
    if (m == 0u) {
        int best = 0; float bv = l[0];
        #pragma unroll
        for (int e = 1; e < 8; e++) if (l[e] > bv) { bv = l[e]; best = e; }
        m = 1u << best;
    }
    int e0 = -1, e1 = -1; float v0 = -INFINITY, v1 = -INFINITY;
    #pragma unroll
    for (int e = 0; e < 8; e++) {
        if ((m >> e) & 1u) {
            float f = l[e];
            if (f > v0)      { v1 = v0; e1 = e0; v0 = f; e0 = e; }
            else if (f > v1) { v1 = f; e1 = e; }
        }
    }
    float w0 = 1.f, w1 = 0.f;
    if (e1 >= 0) {
        float ex = expf(v1 - v0);
        w0 = 1.0f / (1.0f + ex);
        w1 = ex * w0;
    }
    bool has1 = (e1 >= 0 && w1 > 0.f);
    int p0 = atomicAdd(&sCnt[e0], 1);
    int p1 = has1 ? atomicAdd(&sCnt[e1], 1) : -1;
    __syncthreads();
    if (tid < 8) sBase[tid] = atomicAdd(&g_cnt[tid], sCnt[tid]);
    __syncthreads();
    {
        int pos = sBase[e0] + p0;
        g_list[e0*NTOK + pos] = n;
        g_wl[e0*NTOK + pos]   = w0;
    }
    unsigned te = (unsigned)e0 | (255u << 8);
    float tw1 = 0.f;
    if (has1) {
        int pos = sBase[e1] + p1;
        g_list[e1*NTOK + pos] = n;
        g_wl[e1*NTOK + pos]   = w1;
        te = (unsigned)e0 | ((unsigned)e1 << 8);
        tw1 = w1;
    }
    g_te[n] = te; g_tw0[n] = w0; g_tw1[n] = tw1;

    float4 z4 = make_float4(0.f, 0.f, 0.f, 0.f);
    float4* o4 = (float4*)out;
    for (int i = n; i < NTOK*OUTD/4; i += NTOK) o4[i] = z4;
}

// ---------------- fused expert FFN: 512 threads, N-split warps ----------------
__global__ void __launch_bounds__(512) ffn_kernel(
    const float* __restrict__ x,  const float* __restrict__ bw,
    const float* __restrict__ W1, const float* __restrict__ b1,
    const float* __restrict__ W2, const float* __restrict__ b2,
    const float* __restrict__ A1, const float* __restrict__ B1,
    const float* __restrict__ A2, const float* __restrict__ B2,
    float* __restrict__ out)
{
    extern __shared__ float sm[];
    float* sH  = sm;                     // [416][68]; sX aliases rows 0..223
    float* sX  = sm;
    float* sW  = sH + 416*SSTR;          // 2 x 6144 double buffer (also A1 staging)
    float* sBw = sW + 12288;             // [64][4]
    float* sGw = sBw + 256;              // [64]
    int*   sTok = (int*)(sGw + 64);      // [64]

    int e = blockIdx.y;
    int cnt = g_cnt[e];
    int t0 = blockIdx.x * 64;
    if (t0 >= cnt) return;
    int nt = min(64, cnt - t0);
    int tid = threadIdx.x;

    if (tid < 64) {
        int idx = t0 + min(tid, nt - 1);
        int tok = g_list[e*NTOK + idx];
        sTok[tid] = tok;
        sGw[tid]  = (tid < nt) ? g_wl[e*NTOK + idx] : 0.f;
        *(float4*)(sBw + tid*4) = *(const float4*)(bw + (size_t)tok*4);
    }
    __syncthreads();

    {   // gather x rows -> sX[c][t]; 8 parts of 24 floats
        int t = tid & 63, part = tid >> 6;
        int tok = sTok[t];
        const float4* src = (const float4*)(x + (size_t)tok*CIN) + part*6;
        #pragma unroll
        for (int i = 0; i < 6; i++) {
            float4 v = src[i];
            int c = part*24 + i*4;
            sX[(c+0)*SSTR+t]=v.x; sX[(c+1)*SSTR+t]=v.y;
            sX[(c+2)*SSTR+t]=v.z; sX[(c+3)*SSTR+t]=v.w;
        }
        const float4* a4 = (const float4*)(A1 + (size_t)e*6144);
        float4* w4 = (float4*)sW;
        for (int i = tid; i < 1536; i += 512) w4[i] = a4[i];
    }
    __syncthreads();

    // LoRA1: thread = (token, band, r-half); 2 ull accumulators
    {
        int t = tid >> 3, b = (tid >> 1) & 3, h = tid & 1;
        const ull* A = (const ull*)(sW + b*1536) + 2*h;
        ull a0 = 0, a1 = 0;
        for (int c = 0; c < CIN; c++) {
            float xv = sX[c*SSTR + t];
            ull xp = pk2(xv, xv);
            fma2(a0, xp, A[c*4]);
            fma2(a1, xp, A[c*4 + 1]);
        }
        float scl = LSCALE * sBw[t*4 + b];
        float lo, hi;
        upk2(a0, lo, hi);
        sX[(CIN + b*8 + 4*h    )*SSTR + t] = scl*lo;
        sX[(CIN + b*8 + 4*h + 1)*SSTR + t] = scl*hi;
        upk2(a1, lo, hi);
        sX[(CIN + b*8 + 4*h + 2)*SSTR + t] = scl*lo;
        sX[(CIN + b*8 + 4*h + 3)*SSTR + t] = scl*hi;
    }
    __syncthreads();

    int warp = tid >> 5, lane = tid & 31;
    int cg = warp & 1, tw = warp >> 1, m0 = tw * 8;

    // ---- layer 1: [64,224] @ [224,384]; warp = 8 tokens x 192 cols ----
    ull acc1[4][6];
    #pragma unroll
    for (int jj = 0; jj < 6; jj++) {
        float bv = b1[e*HID + cg*192 + lane + 32*jj];
        ull bp = pk2(bv, bv);
        #pragma unroll
        for (int mi = 0; mi < 4; mi++) acc1[mi][jj] = bp;
    }
    const float* W1e = W1 + (size_t)e*CIN*HID;
    const float* B1e = B1 + (size_t)e*32*HID;
    float4 pr[3];
    {   // prologue: tile 0 (rows < 16 -> W1e)
        #pragma unroll
        for (int j = 0; j < 3; j++) {
            int i = tid + j*512;
            int row = i / 96, c4 = i % 96;
            pr[j] = ((const float4*)(W1e + (size_t)row*HID))[c4];
            ((float4*)sW)[row*96 + c4] = pr[j];
        }
    }
    for (int kt = 0; kt < 14; kt++) {
        if (kt < 13) {
            #pragma unroll
            for (int j = 0; j < 3; j++) {
                int i = tid + j*512;
                int row = i / 96, c4 = i % 96;
                int k = (kt+1)*16 + row;
                const float* src = (k < CIN) ? (W1e + (size_t)k*HID)
                                             : (B1e + (size_t)(k - CIN)*HID);
                pr[j] = ((const float4*)src)[c4];
            }
        }
        __syncthreads();
        const float* Wb = sW + (kt & 1)*6144 + cg*192;
        #pragma unroll 4
        for (int kk = 0; kk < 16; kk++) {
            int k = kt*16 + kk;
            const ull* xp = (const ull*)(sX + k*SSTR + m0);
            ull x0 = xp[0], x1 = xp[1], x2 = xp[2], x3 = xp[3];
            #pragma unroll
            for (int jj = 0; jj < 6; jj++) {
                float w = Wb[kk*HID + lane + 32*jj];
                ull wp = pk2(w, w);
                fma2(acc1[0][jj], x0, wp);
                fma2(acc1[1][jj], x1, wp);
                fma2(acc1[2][jj], x2, wp);
                fma2(acc1[3][jj], x3, wp);
            }
        }
        if (kt < 13) {
            float4* d4 = (float4*)(sW + ((kt+1) & 1)*6144);
            #pragma unroll
            for (int j = 0; j < 3; j++) {
                int i = tid + j*512;
                int row = i / 96, c4 = i % 96;
                d4[row*96 + c4] = pr[j];
            }
        }
    }
    __syncthreads();

    // exact GELU -> sH[h][t] (aliases sX)
    #pragma unroll
    for (int mi = 0; mi < 4; mi++)
        #pragma unroll
        for (int jj = 0; jj < 6; jj++) {
            float lo, hi; upk2(acc1[mi][jj], lo, hi);
            float g0 = lo * 0.5f * (1.0f + erff(lo * 0.70710678118654752f));
            float g1 = hi * 0.5f * (1.0f + erff(hi * 0.70710678118654752f));
            int h = cg*192 + lane + 32*jj;
            sH[h*SSTR + m0 + 2*mi    ] = g0;
            sH[h*SSTR + m0 + 2*mi + 1] = g1;
        }
    __syncthreads();

    // LoRA2: thread = (token, band, r-half)
    {
        int t = tid >> 3, b = (tid >> 1) & 3, h = tid & 1;
        const ull* A = (const ull*)(A2 + ((size_t)e*4 + b)*HID*8) + 2*h;
        ull a0 = 0, a1 = 0;
        for (int hh = 0; hh < HID; hh++) {
            float hv = sH[hh*SSTR + t];
            ull xp = pk2(hv, hv);
            fma2(a0, xp, A[hh*4]);
            fma2(a1, xp, A[hh*4 + 1]);
        }
        float scl = LSCALE * sBw[t*4 + b];
        float lo, hi;
        upk2(a0, lo, hi);
        sH[(HID + b*8 + 4*h    )*SSTR + t] = scl*lo;
        sH[(HID + b*8 + 4*h + 1)*SSTR + t] = scl*hi;
        upk2(a1, lo, hi);
        sH[(HID + b*8 + 4*h + 2)*SSTR + t] = scl*lo;
        sH[(HID + b*8 + 4*h + 3)*SSTR + t] = scl*hi;
    }

    // ---- layer 2: [64,416] @ [416,192]; warp = 8 tokens x 96 cols ----
    ull acc2[4][3];
    #pragma unroll
    for (int jj = 0; jj < 3; jj++) {
        float bv = b2[e*OUTD + cg*96 + lane + 32*jj];
        ull bp = pk2(bv, bv);
        #pragma unroll
        for (int mi = 0; mi < 4; mi++) acc2[mi][jj] = bp;
    }
    const float* W2e = W2 + (size_t)e*HID*OUTD;
    const float* B2e = B2 + (size_t)e*32*OUTD;
    float4 qr[2];
    {   // prologue: tile 0
        #pragma unroll
        for (int j = 0; j < 2; j++) {
            int i = tid + j*512;
            if (i < 768) {
                int row = i / 48, c4 = i % 48;
                qr[j] = ((const float4*)(W2e + (size_t)row*OUTD))[c4];
                ((float4*)sW)[row*48 + c4] = qr[j];
            }
        }
    }
    for (int kt = 0; kt < 26; kt++) {
        if (kt < 25) {
            #pragma unroll
            for (int j = 0; j < 2; j++) {
                int i = tid + j*512;
                if (i < 768) {
                    int row = i / 48, c4 = i % 48;
                    int k = (kt+1)*16 + row;
                    const float* src = (k < HID) ? (W2e + (size_t)k*OUTD)
                                                 : (B2e + (size_t)(k - HID)*OUTD);
                    qr[j] = ((const float4*)src)[c4];
                }
            }
        }
        __syncthreads();
        const float* Wb = sW + (kt & 1)*3072 + cg*96;
        #pragma unroll 4
        for (int kk = 0; kk < 16; kk++) {
            int k = kt*16 + kk;
            const ull* xp = (const ull*)(sH + k*SSTR + m0);
            ull x0 = xp[0], x1 = xp[1], x2 = xp[2], x3 = xp[3];
            #pragma unroll
            for (int jj = 0; jj < 3; jj++) {
                float w = Wb[kk*OUTD + lane + 32*jj];
                ull wp = pk2(w, w);
                fma2(acc2[0][jj], x0, wp);
                fma2(acc2[1][jj], x1, wp);
                fma2(acc2[2][jj], x2, wp);
                fma2(acc2[3][jj], x3, wp);
            }
        }
        if (kt < 25) {
            float4* d4 = (float4*)(sW + ((kt+1) & 1)*3072);
            #pragma unroll
            for (int j = 0; j < 2; j++) {
                int i = tid + j*512;
                if (i < 768) {
                    int row = i / 48, c4 = i % 48;
                    d4[row*48 + c4] = qr[j];
                }
            }
        }
    }
    // epilogue
    #pragma unroll
    for (int mi = 0; mi < 4; mi++) {
        #pragma unroll
        for (int half = 0; half < 2; half++) {
            int t = m0 + 2*mi + half;
            if (t < nt) {
                int tok = sTok[t];
                float g = sGw[t];
                #pragma unroll
                for (int jj = 0; jj < 3; jj++) {
                    float lo, hi; upk2(acc2[mi][jj], lo, hi);
                    float v = half ? hi : lo;
                    atomicAdd(&out[(size_t)tok*OUTD + cg*96 + lane + 32*jj], g*v);
                }
            }
        }
    }
}

// ---------------- deterministic loss ----------------
__global__ void __launch_bounds__(1024) loss_kernel(float* out, int out_size) {
    __shared__ float sI[8][32], sL[8][32];
    int tid = threadIdx.x, lane = tid & 31, warp = tid >> 5;
    float imp[8] = {0,0,0,0,0,0,0,0}, ld[8] = {0,0,0,0,0,0,0,0};
    for (int n = tid; n < NTOK; n += 1024) {
        unsigned te = g_te[n];
        int e0 = te & 255u, e1 = (te >> 8) & 255u;
        imp[e0] += g_tw0[n]; ld[e0] += 1.f;
        if (e1 != 255) { imp[e1] += g_tw1[n]; ld[e1] += 1.f; }
    }
    #pragma unroll
    for (int e = 0; e < 8; e++) {
        #pragma unroll
        for (int o = 16; o; o >>= 1) {
            imp[e] += __shfl_xor_sync(0xffffffffu, imp[e], o);
            ld[e]  += __shfl_xor_sync(0xffffffffu, ld[e],  o);
        }
        if (lane == 0) { sI[e][warp] = imp[e]; sL[e][warp] = ld[e]; }
    }
    __syncthreads();
    if (tid == 0) {
        float I[8], L[8], mi = 0.f, ml = 0.f;
        for (int e = 0; e < 8; e++) {
            float a = 0.f, b = 0.f;
            for (int w = 0; w < 32; w++) { a += sI[e][w]; b += sL[e][w]; }
            I[e] = a; L[e] = b; mi += a; ml += b;
        }
        mi *= 0.125f; ml *= 0.125f;
        float vi = 0.f, vl = 0.f;
        for (int e = 0; e < 8; e++) {
            float di = I[e] - mi; vi += di*di;
            float dl = L[e] - ml; vl += dl*dl;
        }
        vi *= 0.125f; vl *= 0.125f;
        float loss = (vi / (mi*mi + 1e-10f) + vl / (ml*ml + 1e-10f)) * 0.01f;
        if (out_size > NTOK*OUTD) out[NTOK*OUTD] = loss;
    }
    for (int i = NTOK*OUTD + 1 + tid; i < out_size; i += 1024) out[i] = 0.f;
}

// ---------------- launch ----------------
extern "C" void kernel_launch(void* const* d_in, const int* in_sizes, int n_in,
                              void* d_out, int out_size) {
    const float* x     = (const float*)d_in[0];
    const float* bw    = (const float*)d_in[1];
    const float* xprev = (const float*)d_in[2];
    const float* Wz    = (const float*)d_in[3];
    const float* lng   = (const float*)d_in[4];
    const float* lnb   = (const float*)d_in[5];
    const float* Wg    = (const float*)d_in[6];
    const float* bg    = (const float*)d_in[7];
    const float* W1    = (const float*)d_in[8];
    const float* b1    = (const float*)d_in[9];
    const float* W2    = (const float*)d_in[10];
    const float* b2    = (const float*)d_in[11];
    const float* A1    = (const float*)d_in[12];
    const float* B1    = (const float*)d_in[13];
    const float* A2    = (const float*)d_in[14];
    const float* B2    = (const float*)d_in[15];
    float* out = (float*)d_out;

    const size_t GATE_SMEM = (size_t)(12288 + 2064 + 258 + 258 + 8 + 32*192) * 4;
    const size_t FFN_SMEM  = (size_t)(416*SSTR + 12288 + 256 + 64 + 64) * 4;
    cudaFuncSetAttribute(gate_kernel, cudaFuncAttributeMaxDynamicSharedMemorySize, (int)GATE_SMEM);
    cudaFuncSetAttribute(ffn_kernel,  cudaFuncAttributeMaxDynamicSharedMemorySize, (int)FFN_SMEM);

    init_kernel<<<1, 32>>>();
    gate_kernel<<<NTOK/32, 1024, GATE_SMEM>>>(x, xprev, Wz, lng, lnb, Wg, bg);
    select_kernel<<<NE, 1024>>>();
    route_kernel<<<NTOK/256, 256>>>(out);
    ffn_kernel<<<dim3(NTOK/64, NE), 512, FFN_SMEM>>>(x, bw, W1, b1, W2, b2,
                                                     A1, B1, A2, B2, out);
    loss_kernel<<<1, 1024>>>(out, out_size);
}

// round 7
// speedup vs baseline: 1.0515x; 1.0515x over previous
#include <cuda_runtime.h>
#include <math.h>
#include <stdint.h>

#define NTOK 65536
#define CIN 192
#define HID 384
#define OUTD 192
#define NE 8
#define KCAP 10240
#define TTILE 32
#define SSTR 34
#define LSCALE 2.0f  /* alpha/r = 16/8 */

typedef unsigned long long ull;

__device__ __forceinline__ ull pk2(float lo, float hi) {
    ull r; asm("mov.b64 %0,{%1,%2};" : "=l"(r) : "f"(lo), "f"(hi)); return r;
}
__device__ __forceinline__ void upk2(ull v, float& lo, float& hi) {
    asm("mov.b64 {%0,%1},%2;" : "=f"(lo), "=f"(hi) : "l"(v));
}
__device__ __forceinline__ void fma2(ull& d, ull a, ull b) {
    asm("fma.rn.f32x2 %0,%1,%2,%0;" : "+l"(d) : "l"(a), "l"(b));
}

// ---------------- device scratch ----------------
__device__ float    g_logits[NE * NTOK];
__device__ unsigned g_mask[NTOK];
__device__ int      g_cnt[NE];
__device__ int      g_list[NE * NTOK];
__device__ float    g_wl[NE * NTOK];
__device__ unsigned g_te[NTOK];
__device__ float    g_tw0[NTOK];
__device__ float    g_tw1[NTOK];

__global__ void init_kernel() {
    if (threadIdx.x < NE) g_cnt[threadIdx.x] = 0;
}

// ---------------- gate: features + LN + logits ----------------
__global__ void __launch_bounds__(1024) gate_kernel(
    const float* __restrict__ x, const float* __restrict__ xprev,
    const float* __restrict__ Wz, const float* __restrict__ lng,
    const float* __restrict__ lnb, const float* __restrict__ Wg,
    const float* __restrict__ bg)
{
    extern __shared__ float sm[];
    float* sWz = sm;            // 12288
    float* sWg = sWz + 12288;   // 2064
    float* sg  = sWg + 2064;    // 258
    float* sb  = sg + 258;      // 258
    float* sbg = sb + 258;      // 8
    float* sX  = sbg + 8;       // 32*192

    int tid = threadIdx.x, lane = tid & 31, warp = tid >> 5;
    int n = blockIdx.x * 32 + warp;

    for (int i = tid; i < 12288; i += 1024) sWz[i] = Wz[i];
    for (int i = tid; i < 2064;  i += 1024) sWg[i] = Wg[i];
    for (int i = tid; i < 258;   i += 1024) { sg[i] = lng[i]; sb[i] = lnb[i]; }
    if (tid < 8) sbg[tid] = bg[tid];

    float xr[6];
    #pragma unroll
    for (int i = 0; i < 6; i++) {
        xr[i] = x[(size_t)n*CIN + lane + 32*i];
        sX[warp*CIN + lane + 32*i] = xr[i];
    }
    float s = 0.f, ss = 0.f;
    #pragma unroll
    for (int i = 0; i < 6; i++) {
        float a = fabsf(xr[i] - xprev[(size_t)n*CIN + lane + 32*i]);
        s += a; ss += a*a;
    }
    #pragma unroll
    for (int o = 16; o; o >>= 1) {
        s  += __shfl_xor_sync(0xffffffffu, s, o);
        ss += __shfl_xor_sync(0xffffffffu, ss, o);
    }
    float dmean = s * (1.0f/192.0f);
    float dvar  = fmaxf((ss - s*dmean) * (1.0f/191.0f), 0.f);
    float mu = log1pf(dmean), sd = log1pf(sqrtf(dvar));

    __syncthreads();

    float z0 = 0.f, z1 = 0.f;
    for (int c = 0; c < CIN; c++) {
        float xv = sX[warp*CIN + c];
        z0 = fmaf(xv, sWz[c*64 + lane],      z0);
        z1 = fmaf(xv, sWz[c*64 + lane + 32], z1);
    }
    float sa = z0 + z1, s2 = z0*z0 + z1*z1;
    #pragma unroll
    for (int i = 0; i < 6; i++) { sa += xr[i]; s2 += xr[i]*xr[i]; }
    if (lane == 0) { sa += mu + sd; s2 += mu*mu + sd*sd; }
    #pragma unroll
    for (int o = 16; o; o >>= 1) {
        sa += __shfl_xor_sync(0xffffffffu, sa, o);
        s2 += __shfl_xor_sync(0xffffffffu, s2, o);
    }
    float m_   = sa * (1.0f/258.0f);
    float rstd = rsqrtf(s2 * (1.0f/258.0f) - m_*m_ + 1e-5f);

    float acc[8] = {0,0,0,0,0,0,0,0};
    #pragma unroll
    for (int i = 0; i < 6; i++) {
        int idx = lane + 32*i;
        float nv = (xr[i] - m_)*rstd*sg[idx] + sb[idx];
        #pragma unroll
        for (int e = 0; e < 8; e++) acc[e] = fmaf(nv, sWg[idx*8 + e], acc[e]);
    }
    {
        int idx = 192 + lane;
        float nv = (z0 - m_)*rstd*sg[idx] + sb[idx];
        #pragma unroll
        for (int e = 0; e < 8; e++) acc[e] = fmaf(nv, sWg[idx*8 + e], acc[e]);
        idx = 224 + lane;
        nv = (z1 - m_)*rstd*sg[idx] + sb[idx];
        #pragma unroll
        for (int e = 0; e < 8; e++) acc[e] = fmaf(nv, sWg[idx*8 + e], acc[e]);
    }
    if (lane == 0) {
        float nv = (mu - m_)*rstd*sg[256] + sb[256];
        #pragma unroll
        for (int e = 0; e < 8; e++) acc[e] = fmaf(nv, sWg[256*8 + e], acc[e]);
        nv = (sd - m_)*rstd*sg[257] + sb[257];
        #pragma unroll
        for (int e = 0; e < 8; e++) acc[e] = fmaf(nv, sWg[257*8 + e], acc[e]);
    }
    #pragma unroll
    for (int e = 0; e < 8; e++) {
        #pragma unroll
        for (int o = 16; o; o >>= 1) acc[e] += __shfl_xor_sync(0xffffffffu, acc[e], o);
    }
    if (lane == 0) {
        #pragma unroll
        for (int e = 0; e < 8; e++) g_logits[e*NTOK + n] = acc[e] + sbg[e];
        g_mask[n] = 0u;
    }
}

// ---------------- expert-choice: radix select top-K per expert ----------------
__device__ __forceinline__ unsigned f2key(float f) {
    unsigned u = __float_as_uint(f);
    return (u & 0x80000000u) ? ~u : (u | 0x80000000u);
}

__global__ void __launch_bounds__(1024) select_kernel() {
    __shared__ unsigned hist[256];
    __shared__ unsigned sh_digit, sh_need;
    __shared__ int ccount[64];
    __shared__ int cbase[64];

    int e = blockIdx.x, tid = threadIdx.x;
    int lane = tid & 31, warp = tid >> 5;
    const float* base = g_logits + (size_t)e * NTOK;

    unsigned prefix = 0, pmask = 0, need = KCAP;
    for (int pass = 0; pass < 4; pass++) {
        int shift = 24 - pass*8;
        if (tid < 256) hist[tid] = 0;
        __syncthreads();
        for (int n = tid; n < NTOK; n += 1024) {
            unsigned k = f2key(base[n]);
            bool act = ((k & pmask) == prefix);
            unsigned dg = act ? ((k >> shift) & 255u) : 0xffffffffu;
            unsigned peers = __match_any_sync(0xffffffffu, dg);
            if (act && (__ffs(peers) - 1) == lane)
                atomicAdd(&hist[dg], (unsigned)__popc(peers));
        }
        __syncthreads();
        if (tid == 0) {
            unsigned cum = 0; int d = 255;
            for (; d > 0; d--) {
                unsigned h = hist[d];
                if (cum + h >= need) break;
                cum += h;
            }
            sh_digit = (unsigned)d;
            sh_need  = need - cum;
        }
        __syncthreads();
        prefix |= sh_digit << shift;
        pmask  |= 0xFFu << shift;
        need    = sh_need;
        __syncthreads();
    }
    unsigned thr = prefix;
    int r = (int)need;   // count of ==thr keys to take, lowest index first

    for (int n = tid; n < NTOK; n += 1024)
        if (f2key(base[n]) > thr) atomicOr(&g_mask[n], 1u << e);

    for (int c = warp; c < 64; c += 32) {
        int cnt = 0;
        for (int s = 0; s < 32; s++) {
            int n = c*1024 + s*32 + lane;
            cnt += (f2key(base[n]) == thr);
        }
        #pragma unroll
        for (int o = 16; o; o >>= 1) cnt += __shfl_xor_sync(0xffffffffu, cnt, o);
        if (lane == 0) ccount[c] = cnt;
    }
    __syncthreads();
    if (tid == 0) {
        int run = 0;
        for (int c = 0; c < 64; c++) { cbase[c] = run; run += ccount[c]; }
    }
    __syncthreads();
    for (int c = warp; c < 64; c += 32) {
        int rank = cbase[c];
        if (rank >= r) continue;
        for (int s = 0; s < 32; s++) {
            int n = c*1024 + s*32 + lane;
            bool p = (f2key(base[n]) == thr);
            unsigned bal = __ballot_sync(0xffffffffu, p);
            int myrank = rank + __popc(bal & ((1u << lane) - 1u));
            if (p && myrank < r) atomicOr(&g_mask[n], 1u << e);
            rank += __popc(bal);
        }
    }
}

// ---------------- routing (block-aggregated dispatch) ----------------
__global__ void __launch_bounds__(256) route_kernel(float* __restrict__ out) {
    __shared__ int sCnt[8], sBase[8];
    int tid = threadIdx.x;
    int n = blockIdx.x * 256 + tid;
    if (tid < 8) sCnt[tid] = 0;
    __syncthreads();

    float l[8];
    #pragma unroll
    for (int e = 0; e < 8; e++) l[e] = g_logits[e*NTOK + n];
    unsigned m = g_mask[n];
    if (m == 0u) {
        int best = 0; float bv = l[0];
        #pragma unroll
        for (int e = 1; e < 8; e++) if (l[e] > bv) { bv = l[e]; best = e; }
        m = 1u << best;
    }
    int e0 = -1, e1 = -1; float v0 = -INFINITY, v1 = -INFINITY;
    #pragma unroll
    for (int e = 0; e < 8; e++) {
        if ((m >> e) & 1u) {
            float f = l[e];
            if (f > v0)      { v1 = v0; e1 = e0; v0 = f; e0 = e; }
            else if (f > v1) { v1 = f; e1 = e; }
        }
    }
    float w0 = 1.f, w1 = 0.f;
    if (e1 >= 0) {
        float ex = expf(v1 - v0);
        w0 = 1.0f / (1.0f + ex);
        w1 = ex * w0;
    }
    bool has1 = (e1 >= 0 && w1 > 0.f);
    int p0 = atomicAdd(&sCnt[e0], 1);
    int p1 = has1 ? atomicAdd(&sCnt[e1], 1) : -1;
    __syncthreads();
    if (tid < 8) sBase[tid] = atomicAdd(&g_cnt[tid], sCnt[tid]);
    __syncthreads();
    {
        int pos = sBase[e0] + p0;
        g_list[e0*NTOK + pos] = n;
        g_wl[e0*NTOK + pos]   = w0;
    }
    unsigned te = (unsigned)e0 | (255u << 8);
    float tw1 = 0.f;
    if (has1) {
        int pos = sBase[e1] + p1;
        g_list[e1*NTOK + pos] = n;
        g_wl[e1*NTOK + pos]   = w1;
        te = (unsigned)e0 | ((unsigned)e1 << 8);
        tw1 = w1;
    }
    g_te[n] = te; g_tw0[n] = w0; g_tw1[n] = tw1;

    float4 z4 = make_float4(0.f, 0.f, 0.f, 0.f);
    float4* o4 = (float4*)out;
    for (int i = n; i < NTOK*OUTD/4; i += NTOK) o4[i] = z4;
}

// ---------------- fused expert FFN: 32-token tiles, 2 CTAs/SM ----------------
__global__ void __launch_bounds__(256, 2) ffn_kernel(
    const float* __restrict__ x,  const float* __restrict__ bw,
    const float* __restrict__ W1, const float* __restrict__ b1,
    const float* __restrict__ W2, const float* __restrict__ b2,
    const float* __restrict__ A1, const float* __restrict__ B1,
    const float* __restrict__ A2, const float* __restrict__ B2,
    float* __restrict__ out)
{
    extern __shared__ float sm[];
    float* sH  = sm;                     // [416][34]; sX aliases rows 0..223
    float* sX  = sm;
    float* sW  = sH + 416*SSTR;          // 2 x 6144 double buffer (also A1 staging)
    float* sBw = sW + 12288;             // [32][4]
    float* sGw = sBw + 128;              // [32]
    int*   sTok = (int*)(sGw + 32);      // [32]

    int e = blockIdx.y;
    int cnt = g_cnt[e];
    int t0 = blockIdx.x * TTILE;
    if (t0 >= cnt) return;
    int nt = min(TTILE, cnt - t0);
    int tid = threadIdx.x;

    if (tid < TTILE) {
        int idx = t0 + min(tid, nt - 1);
        int tok = g_list[e*NTOK + idx];
        sTok[tid] = tok;
        sGw[tid]  = (tid < nt) ? g_wl[e*NTOK + idx] : 0.f;
        *(float4*)(sBw + tid*4) = *(const float4*)(bw + (size_t)tok*4);
    }
    __syncthreads();

    {   // gather x rows -> sX[c][t]; 8 parts of 24 floats
        int t = tid & 31, part = tid >> 5;
        int tok = sTok[t];
        const float4* src = (const float4*)(x + (size_t)tok*CIN) + part*6;
        #pragma unroll
        for (int i = 0; i < 6; i++) {
            float4 v = src[i];
            int c = part*24 + i*4;
            sX[(c+0)*SSTR+t]=v.x; sX[(c+1)*SSTR+t]=v.y;
            sX[(c+2)*SSTR+t]=v.z; sX[(c+3)*SSTR+t]=v.w;
        }
        const float4* a4 = (const float4*)(A1 + (size_t)e*6144);
        float4* w4 = (float4*)sW;
        for (int i = tid; i < 1536; i += 256) w4[i] = a4[i];
    }
    __syncthreads();

    // LoRA1: thread = (token, band, r-half)
    {
        int t = tid >> 3, b = (tid >> 1) & 3, h = tid & 1;
        const ull* A = (const ull*)(sW + b*1536) + 2*h;
        ull a0 = 0, a1 = 0;
        for (int c = 0; c < CIN; c++) {
            float xv = sX[c*SSTR + t];
            ull xp = pk2(xv, xv);
            fma2(a0, xp, A[c*4]);
            fma2(a1, xp, A[c*4 + 1]);
        }
        float scl = LSCALE * sBw[t*4 + b];
        float lo, hi;
        upk2(a0, lo, hi);
        sX[(CIN + b*8 + 4*h    )*SSTR + t] = scl*lo;
        sX[(CIN + b*8 + 4*h + 1)*SSTR + t] = scl*hi;
        upk2(a1, lo, hi);
        sX[(CIN + b*8 + 4*h + 2)*SSTR + t] = scl*lo;
        sX[(CIN + b*8 + 4*h + 3)*SSTR + t] = scl*hi;
    }
    __syncthreads();

    int warp = tid >> 5, lane = tid & 31, m0 = warp * 4;

    // ---- layer 1: [32,224] @ [224,384]; warp = 4 tokens x 384 cols ----
    ull acc1[2][12];
    #pragma unroll
    for (int jj = 0; jj < 12; jj++) {
        float bv = b1[e*HID + lane + 32*jj];
        ull bp = pk2(bv, bv);
        acc1[0][jj] = bp; acc1[1][jj] = bp;
    }
    const float* W1e = W1 + (size_t)e*CIN*HID;
    const float* B1e = B1 + (size_t)e*32*HID;
    float4 pr[6];
    {   // prologue: tile 0 (rows < 16 -> W1e)
        #pragma unroll
        for (int j = 0; j < 6; j++) {
            int i = tid + j*256;
            int row = i / 96, c4 = i % 96;
            pr[j] = ((const float4*)(W1e + (size_t)row*HID))[c4];
            ((float4*)sW)[row*96 + c4] = pr[j];
        }
    }
    for (int kt = 0; kt < 14; kt++) {
        if (kt < 13) {
            #pragma unroll
            for (int j = 0; j < 6; j++) {
                int i = tid + j*256;
                int row = i / 96, c4 = i % 96;
                int k = (kt+1)*16 + row;
                const float* src = (k < CIN) ? (W1e + (size_t)k*HID)
                                             : (B1e + (size_t)(k - CIN)*HID);
                pr[j] = ((const float4*)src)[c4];
            }
        }
        __syncthreads();
        const float* Wb = sW + (kt & 1)*6144;
        #pragma unroll 4
        for (int kk = 0; kk < 16; kk++) {
            int k = kt*16 + kk;
            const ull* xp = (const ull*)(sX + k*SSTR + m0);
            ull x0 = xp[0], x1 = xp[1];
            #pragma unroll
            for (int jj = 0; jj < 12; jj++) {
                float w = Wb[kk*HID + lane + 32*jj];
                ull wp = pk2(w, w);
                fma2(acc1[0][jj], x0, wp);
                fma2(acc1[1][jj], x1, wp);
            }
        }
        if (kt < 13) {
            float4* d4 = (float4*)(sW + ((kt+1) & 1)*6144);
            #pragma unroll
            for (int j = 0; j < 6; j++) {
                int i = tid + j*256;
                int row = i / 96, c4 = i % 96;
                d4[row*96 + c4] = pr[j];
            }
        }
    }
    __syncthreads();

    // exact GELU -> sH[h][t] (aliases sX)
    #pragma unroll
    for (int mi = 0; mi < 2; mi++)
        #pragma unroll
        for (int jj = 0; jj < 12; jj++) {
            float lo, hi; upk2(acc1[mi][jj], lo, hi);
            float g0 = lo * 0.5f * (1.0f + erff(lo * 0.70710678118654752f));
            float g1 = hi * 0.5f * (1.0f + erff(hi * 0.70710678118654752f));
            int h = lane + 32*jj;
            sH[h*SSTR + m0 + 2*mi    ] = g0;
            sH[h*SSTR + m0 + 2*mi + 1] = g1;
        }
    __syncthreads();

    // LoRA2: thread = (token, band, r-half)
    {
        int t = tid >> 3, b = (tid >> 1) & 3, h = tid & 1;
        const ull* A = (const ull*)(A2 + ((size_t)e*4 + b)*HID*8) + 2*h;
        ull a0 = 0, a1 = 0;
        for (int hh = 0; hh < HID; hh++) {
            float hv = sH[hh*SSTR + t];
            ull xp = pk2(hv, hv);
            fma2(a0, xp, A[hh*4]);
            fma2(a1, xp, A[hh*4 + 1]);
        }
        float scl = LSCALE * sBw[t*4 + b];
        float lo, hi;
        upk2(a0, lo, hi);
        sH[(HID + b*8 + 4*h    )*SSTR + t] = scl*lo;
        sH[(HID + b*8 + 4*h + 1)*SSTR + t] = scl*hi;
        upk2(a1, lo, hi);
        sH[(HID + b*8 + 4*h + 2)*SSTR + t] = scl*lo;
        sH[(HID + b*8 + 4*h + 3)*SSTR + t] = scl*hi;
    }

    // ---- layer 2: [32,416] @ [416,192]; warp = 4 tokens x 192 cols ----
    ull acc2[2][6];
    #pragma unroll
    for (int jj = 0; jj < 6; jj++) {
        float bv = b2[e*OUTD + lane + 32*jj];
        ull bp = pk2(bv, bv);
        acc2[0][jj] = bp; acc2[1][jj] = bp;
    }
    const float* W2e = W2 + (size_t)e*HID*OUTD;
    const float* B2e = B2 + (size_t)e*32*OUTD;
    float4 qr[3];
    {   // prologue: tile 0
        #pragma unroll
        for (int j = 0; j < 3; j++) {
            int i = tid + j*256;
            int row = i / 48, c4 = i % 48;
            qr[j] = ((const float4*)(W2e + (size_t)row*OUTD))[c4];
            ((float4*)sW)[row*48 + c4] = qr[j];
        }
    }
    for (int kt = 0; kt < 26; kt++) {
        if (kt < 25) {
            #pragma unroll
            for (int j = 0; j < 3; j++) {
                int i = tid + j*256;
                int row = i / 48, c4 = i % 48;
                int k = (kt+1)*16 + row;
                const float* src = (k < HID) ? (W2e + (size_t)k*OUTD)
                                             : (B2e + (size_t)(k - HID)*OUTD);
                qr[j] = ((const float4*)src)[c4];
            }
        }
        __syncthreads();
        const float* Wb = sW + (kt & 1)*3072;
        #pragma unroll 4
        for (int kk = 0; kk < 16; kk++) {
            int k = kt*16 + kk;
            const ull* xp = (const ull*)(sH + k*SSTR + m0);
            ull x0 = xp[0], x1 = xp[1];
            #pragma unroll
            for (int jj = 0; jj < 6; jj++) {
                float w = Wb[kk*OUTD + lane + 32*jj];
                ull wp = pk2(w, w);
                fma2(acc2[0][jj], x0, wp);
                fma2(acc2[1][jj], x1, wp);
            }
        }
        if (kt < 25) {
            float4* d4 = (float4*)(sW + ((kt+1) & 1)*3072);
            #pragma unroll
            for (int j = 0; j < 3; j++) {
                int i = tid + j*256;
                int row = i / 48, c4 = i % 48;
                d4[row*48 + c4] = qr[j];
            }
        }
    }
    // epilogue
    #pragma unroll
    for (int mi = 0; mi < 2; mi++) {
        #pragma unroll
        for (int half = 0; half < 2; half++) {
            int t = m0 + 2*mi + half;
            if (t < nt) {
                int tok = sTok[t];
                float g = sGw[t];
                #pragma unroll
                for (int jj = 0; jj < 6; jj++) {
                    float lo, hi; upk2(acc2[mi][jj], lo, hi);
                    float v = half ? hi : lo;
                    atomicAdd(&out[(size_t)tok*OUTD + lane + 32*jj], g*v);
                }
            }
        }
    }
}

// ---------------- deterministic loss ----------------
__global__ void __launch_bounds__(1024) loss_kernel(float* out, int out_size) {
    __shared__ float sI[8][32], sL[8][32];
    int tid = threadIdx.x, lane = tid & 31, warp = tid >> 5;
    float imp[8] = {0,0,0,0,0,0,0,0}, ld[8] = {0,0,0,0,0,0,0,0};
    for (int n = tid; n < NTOK; n += 1024) {
        unsigned te = g_te[n];
        int e0 = te & 255u, e1 = (te >> 8) & 255u;
        imp[e0] += g_tw0[n]; ld[e0] += 1.f;
        if (e1 != 255) { imp[e1] += g_tw1[n]; ld[e1] += 1.f; }
    }
    #pragma unroll
    for (int e = 0; e < 8; e++) {
        #pragma unroll
        for (int o = 16; o; o >>= 1) {
            imp[e] += __shfl_xor_sync(0xffffffffu, imp[e], o);
            ld[e]  += __shfl_xor_sync(0xffffffffu, ld[e],  o);
        }
        if (lane == 0) { sI[e][warp] = imp[e]; sL[e][warp] = ld[e]; }
    }
    __syncthreads();
    if (tid == 0) {
        float I[8], L[8], mi = 0.f, ml = 0.f;
        for (int e = 0; e < 8; e++) {
            float a = 0.f, b = 0.f;
            for (int w = 0; w < 32; w++) { a += sI[e][w]; b += sL[e][w]; }
            I[e] = a; L[e] = b; mi += a; ml += b;
        }
        mi *= 0.125f; ml *= 0.125f;
        float vi = 0.f, vl = 0.f;
        for (int e = 0; e < 8; e++) {
            float di = I[e] - mi; vi += di*di;
            float dl = L[e] - ml; vl += dl*dl;
        }
        vi *= 0.125f; vl *= 0.125f;
        float loss = (vi / (mi*mi + 1e-10f) + vl / (ml*ml + 1e-10f)) * 0.01f;
        if (out_size > NTOK*OUTD) out[NTOK*OUTD] = loss;
    }
    for (int i = NTOK*OUTD + 1 + tid; i < out_size; i += 1024) out[i] = 0.f;
}

// ---------------- launch ----------------
extern "C" void kernel_launch(void* const* d_in, const int* in_sizes, int n_in,
                              void* d_out, int out_size) {
    const float* x     = (const float*)d_in[0];
    const float* bw    = (const float*)d_in[1];
    const float* xprev = (const float*)d_in[2];
    const float* Wz    = (const float*)d_in[3];
    const float* lng   = (const float*)d_in[4];
    const float* lnb   = (const float*)d_in[5];
    const float* Wg    = (const float*)d_in[6];
    const float* bg    = (const float*)d_in[7];
    const float* W1    = (const float*)d_in[8];
    const float* b1    = (const float*)d_in[9];
    const float* W2    = (const float*)d_in[10];
    const float* b2    = (const float*)d_in[11];
    const float* A1    = (const float*)d_in[12];
    const float* B1    = (const float*)d_in[13];
    const float* A2    = (const float*)d_in[14];
    const float* B2    = (const float*)d_in[15];
    float* out = (float*)d_out;

    const size_t GATE_SMEM = (size_t)(12288 + 2064 + 258 + 258 + 8 + 32*192) * 4;
    const size_t FFN_SMEM  = (size_t)(416*SSTR + 12288 + 128 + 32 + 32) * 4;
    cudaFuncSetAttribute(gate_kernel, cudaFuncAttributeMaxDynamicSharedMemorySize, (int)GATE_SMEM);
    cudaFuncSetAttribute(ffn_kernel,  cudaFuncAttributeMaxDynamicSharedMemorySize, (int)FFN_SMEM);

    init_kernel<<<1, 32>>>();
    gate_kernel<<<NTOK/32, 1024, GATE_SMEM>>>(x, xprev, Wz, lng, lnb, Wg, bg);
    select_kernel<<<NE, 1024>>>();
    route_kernel<<<NTOK/256, 256>>>(out);
    ffn_kernel<<<dim3(NTOK/TTILE, NE), 256, FFN_SMEM>>>(x, bw, W1, b1, W2, b2,
                                                        A1, B1, A2, B2, out);
    loss_kernel<<<1, 1024>>>(out, out_size);
}